// round 11
// baseline (speedup 1.0000x reference)
#include <cuda_runtime.h>
#include <cstddef>

// Problem constants (fixed by the dataset problem)
#define CC 32
#define HH 128
#define WW 512
#define PAD 40
#define DD (PAD + 1)

// out[c,d,h,w] = in1[c,h,w] * (w >= d ? in2[c,h,w-d] : 0)
//
// One CTA per (c,h) row (4096 CTAs, 128 threads). in2 row staged once into
// shared memory with a PAD-float zero apron. Thread t owns the aligned float4
// at w = 4t; the shifted in2 window lives in 4 rotating registers.
//
// d-loop unrolled by 4: from one window state (b0..b3 = W[base-d..base-d+3])
// planes d..d+3 are formed using four INDEPENDENT carries (prev-lane
// b3,b2,b1,b0 = W[base-d-1..base-d-4]) fetched by four parallel SHFL.UPs at
// the top of the iteration; the window then advances by 4 as a register
// permutation. Per-plane SHFL dependency-chain cost drops from 26 cyc (R5)
// -> 13 (R10, x2) -> ~6.5 here, so stores issue nearly back-to-back. Only
// lane 0 touches shared in the loop (conflict-free apron reads). Stores are
// evict-first streaming (__stcs): write-through (R9) regressed.
__global__ __launch_bounds__(128) void corr1d_row_kernel(
    const float* __restrict__ in1,
    const float* __restrict__ in2,
    float* __restrict__ out)
{
    __shared__ float s2[PAD + WW];   // 552 floats; [0,PAD) is the zero apron

    const int row  = blockIdx.x;     // (c,h) in [0, C*H)
    const int t    = threadIdx.x;    // 0..127
    const int lane = t & 31;
    const int c    = row / HH;
    const int h    = row % HH;

    // Stage rows. PAD*4 = 160 bytes, 16B-aligned, so float4 stores into
    // s2+PAD are legal.
    const float4 a = reinterpret_cast<const float4*>(in1 + (size_t)row * WW)[t];
    if (t < PAD) s2[t] = 0.0f;
    reinterpret_cast<float4*>(s2 + PAD)[t] =
        reinterpret_cast<const float4*>(in2 + (size_t)row * WW)[t];
    __syncthreads();

    // Output base for d=0 plane of this (c,h) row; planes are HH*WW apart.
    float4* po = reinterpret_cast<float4*>(
        out + ((size_t)(c * DD) * HH + h) * WW) + t;
    const size_t plane_stride_v4 = (size_t)HH * WW / 4;   // 16384 float4s

    // d=0 window: one aligned LDS.128.
    float4 b = reinterpret_cast<const float4*>(s2 + PAD)[t];
    float b0 = b.x, b1 = b.y, b2 = b.z, b3 = b.w;

    const int base = PAD + 4 * t;    // s2 index of b0 at d=0

    // Planes 0..39 in groups of 4; plane 40 handled after the loop.
    #pragma unroll
    for (int d = 0; d < PAD; d += 4) {
        // Four independent carries, issued in parallel:
        // ck = W[base - d - k], k = 1..4.
        float c1 = __shfl_up_sync(0xffffffffu, b3, 1);
        float c2 = __shfl_up_sync(0xffffffffu, b2, 1);
        float c3 = __shfl_up_sync(0xffffffffu, b1, 1);
        float c4 = __shfl_up_sync(0xffffffffu, b0, 1);
        if (lane == 0) {
            c1 = s2[base - d - 1];   // warp-boundary fills (apron-safe)
            c2 = s2[base - d - 2];
            c3 = s2[base - d - 3];
            c4 = s2[base - d - 4];
        }

        float4 r;

        // Plane d: (b0, b1, b2, b3)
        r.x = a.x * b0; r.y = a.y * b1; r.z = a.z * b2; r.w = a.w * b3;
        __stcs(po + (size_t)(d + 0) * plane_stride_v4, r);

        // Plane d+1: (c1, b0, b1, b2)
        r.x = a.x * c1; r.y = a.y * b0; r.z = a.z * b1; r.w = a.w * b2;
        __stcs(po + (size_t)(d + 1) * plane_stride_v4, r);

        // Plane d+2: (c2, c1, b0, b1)
        r.x = a.x * c2; r.y = a.y * c1; r.z = a.z * b0; r.w = a.w * b1;
        __stcs(po + (size_t)(d + 2) * plane_stride_v4, r);

        // Plane d+3: (c3, c2, c1, b0)
        r.x = a.x * c3; r.y = a.y * c2; r.z = a.z * c1; r.w = a.w * b0;
        __stcs(po + (size_t)(d + 3) * plane_stride_v4, r);

        // Advance window by 4 disparities: W[base-d-4 .. base-d-1].
        b0 = c4;
        b1 = c3;
        b2 = c2;
        b3 = c1;
    }

    // Final plane d = PAD (window now holds W[base-PAD .. base-PAD+3]).
    float4 r;
    r.x = a.x * b0;
    r.y = a.y * b1;
    r.z = a.z * b2;
    r.w = a.w * b3;
    __stcs(po + (size_t)PAD * plane_stride_v4, r);
}

extern "C" void kernel_launch(void* const* d_in, const int* in_sizes, int n_in,
                              void* d_out, int out_size)
{
    const float* in1 = (const float*)d_in[0];
    const float* in2 = (const float*)d_in[1];
    float* out = (float*)d_out;

    corr1d_row_kernel<<<CC * HH, WW / 4>>>(in1, in2, out);
}